// round 1
// baseline (speedup 1.0000x reference)
#include <cuda_runtime.h>

// FewShotNCALoss: N=8192 points, D=256, 64 classes, temperature scalar.
// loss = -mean_j over valid of log( num_j / (num_j + den_j) )
//   num_j = sum_{i != j, t_i == t_j} exp(-||xi-xj||^2 / T)
//   den_j = max(sum_{t_i != t_j} exp(-||xi-xj||^2 / T), 1e-10)
// Reduced to per-class column sums: S_tot[j], S_same[j]; diagonal dist == 1.0f.
// Upper-triangle tiling (symmetry) halves FMA + EX2 work.

#define NROWS 8192
#define DIM   256
#define NCLS  64

#define BM 128
#define BN 128
#define BK 16
#define TM 8
#define TN 8
#define PAD 4
#define BMP (BM + PAD)

__device__ float g_sq[NROWS];     // ||x_i||^2
__device__ float g_tot[NROWS];    // S_tot[j]
__device__ float g_same[NROWS];   // S_same[j]
__device__ int   g_cls[NROWS];
__device__ int   g_is64;

__device__ __forceinline__ float fast_exp2(float x) {
    float y;
    asm("ex2.approx.ftz.f32 %0, %1;" : "=f"(y) : "f"(x));
    return y;
}

// Detect whether target buffer is int64 or int32 (JAX default x64-off yields int32
// even though the reference asks for int64). Interpreting an int32 class buffer
// (values 0..63) as int64 gives values >= 2^32 with overwhelming probability.
__global__ void detect_kernel(const void* target) {
    const long long* t64 = (const long long*)target;
    int ok = 1;
    for (int i = 0; i < 128; i++) {
        long long v = t64[i];
        if (v < 0 || v >= NCLS) { ok = 0; break; }
    }
    g_is64 = ok;
}

// One warp per row: ||x_i||^2, zero accumulators, convert class labels.
__global__ void prep_kernel(const float* __restrict__ pred, const void* __restrict__ target) {
    int warp = (blockIdx.x * blockDim.x + threadIdx.x) >> 5;
    int lane = threadIdx.x & 31;
    if (warp >= NROWS) return;
    const float* row = pred + (size_t)warp * DIM;
    float s = 0.f;
#pragma unroll
    for (int k = 0; k < DIM / 32; k++) {
        float v = row[lane + k * 32];
        s += v * v;
    }
#pragma unroll
    for (int o = 16; o; o >>= 1) s += __shfl_xor_sync(0xffffffffu, s, o);
    if (lane == 0) {
        g_sq[warp]   = s;
        g_tot[warp]  = 0.f;
        g_same[warp] = 0.f;
        int c;
        if (g_is64) c = (int)((const long long*)target)[warp];
        else        c = ((const int*)target)[warp];
        g_cls[warp] = c;
    }
}

// 128x128 tile of the Gram matrix (classic SGEMM register blocking), fused
// exp epilogue + per-class column/row sum accumulation. Upper triangle only.
__global__ __launch_bounds__(256, 2)
void tile_kernel(const float* __restrict__ pred, const float* __restrict__ temp_ptr) {
    int bi = blockIdx.y, bj = blockIdx.x;
    if (bj < bi) return;
    const int Ibase = bi * BM;
    const int Jbase = bj * BN;
    const int tid = threadIdx.x;
    const int tx = tid & 15;   // n direction
    const int ty = tid >> 4;   // m direction

    __shared__ float As[BK][BMP];
    __shared__ float Bs[BK][BMP];
    __shared__ float sSqI[BM], sSqJ[BN];
    __shared__ int   sClsI[BM], sClsJ[BN];
    __shared__ float sColTot[BN], sColSame[BN], sRowTot[BM], sRowSame[BM];

    if (tid < 128) {
        sSqI[tid]  = g_sq[Ibase + tid];
        sSqJ[tid]  = g_sq[Jbase + tid];
        sClsI[tid] = g_cls[Ibase + tid];
        sClsJ[tid] = g_cls[Jbase + tid];
        sColTot[tid] = 0.f; sColSame[tid] = 0.f;
        sRowTot[tid] = 0.f; sRowSame[tid] = 0.f;
    }

    const float* Ag = pred + (size_t)Ibase * DIM;
    const float* Bg = pred + (size_t)Jbase * DIM;

    float acc[TM][TN];
#pragma unroll
    for (int m = 0; m < TM; m++)
#pragma unroll
        for (int n = 0; n < TN; n++) acc[m][n] = 0.f;

    for (int k0 = 0; k0 < DIM; k0 += BK) {
#pragma unroll
        for (int q = 0; q < 2; q++) {
            int idx = tid + q * 256;       // 0..511
            int r   = idx >> 2;            // 0..127 (tile row)
            int c4  = (idx & 3) << 2;      // 0,4,8,12 within k-slab
            float4 av = *(const float4*)(Ag + (size_t)r * DIM + k0 + c4);
            As[c4 + 0][r] = av.x; As[c4 + 1][r] = av.y;
            As[c4 + 2][r] = av.z; As[c4 + 3][r] = av.w;
            float4 bv = *(const float4*)(Bg + (size_t)r * DIM + k0 + c4);
            Bs[c4 + 0][r] = bv.x; Bs[c4 + 1][r] = bv.y;
            Bs[c4 + 2][r] = bv.z; Bs[c4 + 3][r] = bv.w;
        }
        __syncthreads();
#pragma unroll
        for (int k = 0; k < BK; k++) {
            float a[TM], b[TN];
#pragma unroll
            for (int m = 0; m < TM; m++) a[m] = As[k][ty * TM + m];
#pragma unroll
            for (int n = 0; n < TN; n++) b[n] = Bs[k][tx * TN + n];
#pragma unroll
            for (int m = 0; m < TM; m++)
#pragma unroll
                for (int n = 0; n < TN; n++)
                    acc[m][n] = fmaf(a[m], b[n], acc[m][n]);
        }
        __syncthreads();
    }

    // Epilogue: dist = exp2( (2*G - sq_i - sq_j) * log2(e)/T )
    const float T  = *temp_ptr;
    const float sc = 1.4426950408889634f / T;

    float sj[TN]; int cj[TN];
#pragma unroll
    for (int n = 0; n < TN; n++) { sj[n] = sSqJ[tx * TN + n]; cj[n] = sClsJ[tx * TN + n]; }

    float cT[TN], cS[TN];
#pragma unroll
    for (int n = 0; n < TN; n++) { cT[n] = 0.f; cS[n] = 0.f; }

#pragma unroll
    for (int m = 0; m < TM; m++) {
        float sim = sSqI[ty * TM + m];
        int   cim = sClsI[ty * TM + m];
        float rt = 0.f, rs = 0.f;
#pragma unroll
        for (int n = 0; n < TN; n++) {
            float arg = fmaf(2.f, acc[m][n], -(sim + sj[n])) * sc;
            float d = fast_exp2(arg);
            rt += d; cT[n] += d;
            if (cim == cj[n]) { rs += d; cS[n] += d; }
        }
        atomicAdd(&sRowTot[ty * TM + m], rt);
        atomicAdd(&sRowSame[ty * TM + m], rs);
    }
#pragma unroll
    for (int n = 0; n < TN; n++) {
        atomicAdd(&sColTot[tx * TN + n], cT[n]);
        atomicAdd(&sColSame[tx * TN + n], cS[n]);
    }
    __syncthreads();

    if (tid < 128) {
        atomicAdd(&g_tot[Jbase + tid],  sColTot[tid]);
        atomicAdd(&g_same[Jbase + tid], sColSame[tid]);
        if (bi != bj) {
            // symmetric contribution: column sums for the I block
            atomicAdd(&g_tot[Ibase + tid],  sRowTot[tid]);
            atomicAdd(&g_same[Ibase + tid], sRowSame[tid]);
        }
    }
}

// Deterministic single-block final reduction.
__global__ void loss_kernel(float* __restrict__ out) {
    __shared__ float red[256];
    int tid = threadIdx.x;
    float local = 0.f;
    for (int j = tid; j < NROWS; j += 256) {
        float sm = g_same[j];
        float tt = g_tot[j];
        float num = sm - 1.0f;                 // remove diagonal (dist_jj == 1.0f)
        float den = fmaxf(tt - sm, 1e-10f);
        float frac = num / (num + den);
        if (frac >= 1e-10f) local += logf(frac);
    }
    red[tid] = local;
    __syncthreads();
    for (int o = 128; o; o >>= 1) {
        if (tid < o) red[tid] += red[tid + o];
        __syncthreads();
    }
    if (tid == 0) out[0] = -red[0] / (float)NROWS;
}

extern "C" void kernel_launch(void* const* d_in, const int* in_sizes, int n_in,
                              void* d_out, int out_size) {
    const float* pred   = (const float*)d_in[0];
    const void*  target = d_in[1];
    const float* temp   = (const float*)d_in[2];

    detect_kernel<<<1, 1>>>(target);
    prep_kernel<<<(NROWS * 32 + 255) / 256, 256>>>(pred, target);
    dim3 grid(NROWS / BN, NROWS / BM);   // 64 x 64, upper triangle active
    tile_kernel<<<grid, 256>>>(pred, temp);
    loss_kernel<<<1, 256>>>((float*)d_out);
}

// round 6
// speedup vs baseline: 2.0776x; 2.0776x over previous
#include <cuda_runtime.h>
#include <cstdint>

// FewShotNCALoss via tf32 mma.sync (HMMA) triangle Gram.
//   S_tot[j] = sum_i dist_ij, S_same[j] = sum_{t_i==t_j} dist_ij
//   num_j = S_same[j] - 1.0 (diagonal), den_j = max(S_tot-S_same, eps)
// Upper-triangle tiling: off-diagonal tile contributes column sums (J block)
// and row sums (I block, by symmetry).

#define NROWS 8192
#define DIM   256
#define NCLS  64

#define BM 128
#define BN 128
#define BK 32
#define NKC (DIM / BK)      // 8 k-chunks
#define AST 36              // smem row stride (floats): conflict-free frag loads

// dynamic smem layout (floats)
#define TILE_FLOATS (BM * AST)            // 4608 floats per tile per stage
#define OFF_A(s)  ((s) * TILE_FLOATS)
#define OFF_B(s)  (2 * TILE_FLOATS + (s) * TILE_FLOATS)
#define OFF_SQI   (4 * TILE_FLOATS)
#define OFF_SQJ   (OFF_SQI + 128)
#define OFF_CLSI  (OFF_SQJ + 128)
#define OFF_CLSJ  (OFF_CLSI + 128)
#define OFF_RT    (OFF_CLSJ + 128)
#define OFF_RS    (OFF_RT + 128)
#define OFF_CT    (OFF_RS + 128)
#define OFF_CS    (OFF_CT + 128)
#define SMEM_FLOATS (OFF_CS + 128)
#define SMEM_BYTES  (SMEM_FLOATS * 4)         // 77824

__device__ float g_sq[NROWS];
__device__ float g_tot[NROWS];
__device__ float g_same[NROWS];
__device__ int   g_cls[NROWS];
__device__ int   g_is64;

__device__ __forceinline__ uint32_t smem_u32(const void* p) {
    uint32_t a;
    asm("{ .reg .u64 t; cvta.to.shared.u64 t, %1; cvt.u32.u64 %0, t; }" : "=r"(a) : "l"(p));
    return a;
}
__device__ __forceinline__ float fast_exp2(float x) {
    float y; asm("ex2.approx.ftz.f32 %0, %1;" : "=f"(y) : "f"(x)); return y;
}
__device__ __forceinline__ void cp16(uint32_t dst, const float* src) {
    asm volatile("cp.async.cg.shared.global [%0], [%1], 16;" :: "r"(dst), "l"(src) : "memory");
}
#define CP_COMMIT()  asm volatile("cp.async.commit_group;" ::: "memory")
#define CP_WAIT(n)   asm volatile("cp.async.wait_group %0;" :: "n"(n) : "memory")

__device__ __forceinline__ void mma_tf32(float* c, const uint32_t* a, const uint32_t* b) {
    asm volatile(
        "mma.sync.aligned.m16n8k8.row.col.f32.tf32.tf32.f32 "
        "{%0,%1,%2,%3}, {%4,%5,%6,%7}, {%8,%9}, {%0,%1,%2,%3};"
        : "+f"(c[0]), "+f"(c[1]), "+f"(c[2]), "+f"(c[3])
        : "r"(a[0]), "r"(a[1]), "r"(a[2]), "r"(a[3]), "r"(b[0]), "r"(b[1]));
}

// -------------------- small kernels --------------------
__global__ void detect_kernel(const void* target) {
    __shared__ int bad;
    if (threadIdx.x == 0) bad = 0;
    __syncthreads();
    long long v = ((const long long*)target)[threadIdx.x];
    if (v < 0 || v >= NCLS) atomicAdd(&bad, 1);
    __syncthreads();
    if (threadIdx.x == 0) g_is64 = (bad == 0);
}

__global__ void prep_kernel(const float* __restrict__ pred, const void* __restrict__ target) {
    int warp = (blockIdx.x * blockDim.x + threadIdx.x) >> 5;
    int lane = threadIdx.x & 31;
    if (warp >= NROWS) return;
    const float4* r4 = (const float4*)(pred + (size_t)warp * DIM);
    float4 a = r4[lane], b = r4[lane + 32];
    float s = a.x*a.x + a.y*a.y + a.z*a.z + a.w*a.w
            + b.x*b.x + b.y*b.y + b.z*b.z + b.w*b.w;
#pragma unroll
    for (int o = 16; o; o >>= 1) s += __shfl_xor_sync(0xffffffffu, s, o);
    if (lane == 0) {
        g_sq[warp] = s;
        g_tot[warp] = 0.f;
        g_same[warp] = 0.f;
        g_cls[warp] = g_is64 ? (int)((const long long*)target)[warp]
                             : ((const int*)target)[warp];
    }
}

// -------------------- main tile kernel --------------------
__global__ __launch_bounds__(256, 2)
void tile_kernel(const float* __restrict__ pred, const float* __restrict__ temp_ptr) {
    const int bi = blockIdx.y, bj = blockIdx.x;
    if (bj < bi) return;
    const int Ibase = bi * BM;
    const int Jbase = bj * BN;
    const int tid  = threadIdx.x;
    const int lane = tid & 31;
    const int warp = tid >> 5;
    const int gid  = lane >> 2;     // 0..7
    const int tg   = lane & 3;      // 0..3
    const int m0   = (warp >> 1) * 32;   // warp m-offset
    const int n0   = (warp & 1) * 64;    // warp n-offset

    extern __shared__ float sm[];
    const uint32_t sbase = smem_u32(sm);
    float* sSqI  = sm + OFF_SQI;
    float* sSqJ  = sm + OFF_SQJ;
    int*   sClsI = (int*)(sm + OFF_CLSI);
    int*   sClsJ = (int*)(sm + OFF_CLSJ);
    float* sRT = sm + OFF_RT;  float* sRS = sm + OFF_RS;
    float* sCT = sm + OFF_CT;  float* sCS = sm + OFF_CS;

    if (tid < 128) {
        sSqI[tid]  = g_sq[Ibase + tid];
        sSqJ[tid]  = g_sq[Jbase + tid];
        sClsI[tid] = g_cls[Ibase + tid];
        sClsJ[tid] = g_cls[Jbase + tid];
        sRT[tid] = 0.f; sRS[tid] = 0.f; sCT[tid] = 0.f; sCS[tid] = 0.f;
    }

    const float* Ag = pred + (size_t)Ibase * DIM;
    const float* Bg = pred + (size_t)Jbase * DIM;

    // loader: stage s covers k-chunk [k0, k0+32). 1024 float4 per tile pair.
    auto load_stage = [&](int s, int k0) {
#pragma unroll
        for (int q = 0; q < 4; q++) {
            int idx = tid + q * 256;      // 0..1023
            int r   = idx >> 3;           // 0..127
            int c4  = (idx & 7) * 4;      // 0..28
            cp16(sbase + (OFF_A(s) + r * AST + c4) * 4, Ag + (size_t)r * DIM + k0 + c4);
            cp16(sbase + (OFF_B(s) + r * AST + c4) * 4, Bg + (size_t)r * DIM + k0 + c4);
        }
        CP_COMMIT();
    };

    float acc[2][8][4];
#pragma unroll
    for (int mi = 0; mi < 2; mi++)
#pragma unroll
        for (int nt = 0; nt < 8; nt++)
#pragma unroll
            for (int ci = 0; ci < 4; ci++) acc[mi][nt][ci] = 0.f;

    load_stage(0, 0);

    for (int c = 0; c < NKC; c++) {
        if (c + 1 < NKC) load_stage((c + 1) & 1, (c + 1) * BK);
        if (c + 1 < NKC) CP_WAIT(1); else CP_WAIT(0);
        __syncthreads();

        const float* As = sm + OFF_A(c & 1);
        const float* Bs = sm + OFF_B(c & 1);
#pragma unroll
        for (int ks = 0; ks < 4; ks++) {
            const int kk = ks * 8;
            uint32_t af[2][4], bf[8][2];
#pragma unroll
            for (int mi = 0; mi < 2; mi++) {
                const float* ap = As + (m0 + 16 * mi + gid) * AST + kk + tg;
                af[mi][0] = __float_as_uint(ap[0]);
                af[mi][1] = __float_as_uint(ap[8 * AST]);
                af[mi][2] = __float_as_uint(ap[4]);
                af[mi][3] = __float_as_uint(ap[8 * AST + 4]);
            }
#pragma unroll
            for (int nt = 0; nt < 8; nt++) {
                const float* bp = Bs + (n0 + 8 * nt + gid) * AST + kk + tg;
                bf[nt][0] = __float_as_uint(bp[0]);
                bf[nt][1] = __float_as_uint(bp[4]);
            }
#pragma unroll
            for (int mi = 0; mi < 2; mi++)
#pragma unroll
                for (int nt = 0; nt < 8; nt++)
                    mma_tf32(acc[mi][nt], af[mi], bf[nt]);
        }
        __syncthreads();
    }

    // ---- epilogue ----
    const float negsc = -1.4426950408889634f / (*temp_ptr);

    float colT[16], colS[16];
#pragma unroll
    for (int q = 0; q < 16; q++) { colT[q] = 0.f; colS[q] = 0.f; }

#pragma unroll
    for (int mi = 0; mi < 2; mi++) {
        const int mlo = m0 + 16 * mi + gid;     // rows mlo, mlo+8
        const float si0 = sSqI[mlo],  si1 = sSqI[mlo + 8];
        const int   ci0 = sClsI[mlo], ci1 = sClsI[mlo + 8];
        float rt0 = 0.f, rs0 = 0.f, rt1 = 0.f, rs1 = 0.f;
#pragma unroll
        for (int nt = 0; nt < 8; nt++) {
#pragma unroll
            for (int p = 0; p < 2; p++) {
                const int n = n0 + 8 * nt + 2 * tg + p;
                const float sj = sSqJ[n];
                const int   cj = sClsJ[n];
                float p0 = fmaxf(fmaf(-2.f, acc[mi][nt][p],     si0 + sj), 1e-10f);
                float p1 = fmaxf(fmaf(-2.f, acc[mi][nt][2 + p], si1 + sj), 1e-10f);
                float d0 = fast_exp2(p0 * negsc);
                float d1 = fast_exp2(p1 * negsc);
                rt0 += d0; rt1 += d1;
                colT[nt * 2 + p] += d0 + d1;
                float s0 = (ci0 == cj) ? d0 : 0.f;
                float s1 = (ci1 == cj) ? d1 : 0.f;
                rs0 += s0; rs1 += s1;
                colS[nt * 2 + p] += s0 + s1;
            }
        }
        atomicAdd(&sRT[mlo], rt0);     atomicAdd(&sRS[mlo], rs0);
        atomicAdd(&sRT[mlo + 8], rt1); atomicAdd(&sRS[mlo + 8], rs1);
    }
#pragma unroll
    for (int nt = 0; nt < 8; nt++)
#pragma unroll
        for (int p = 0; p < 2; p++) {
            const int n = n0 + 8 * nt + 2 * tg + p;
            atomicAdd(&sCT[n], colT[nt * 2 + p]);
            atomicAdd(&sCS[n], colS[nt * 2 + p]);
        }
    __syncthreads();

    if (tid < 128) {
        atomicAdd(&g_tot[Jbase + tid],  sCT[tid]);
        atomicAdd(&g_same[Jbase + tid], sCS[tid]);
        if (bi != bj) {
            atomicAdd(&g_tot[Ibase + tid],  sRT[tid]);
            atomicAdd(&g_same[Ibase + tid], sRS[tid]);
        }
    }
}

__global__ void loss_kernel(float* __restrict__ out) {
    int tid = threadIdx.x;
    float local = 0.f;
    for (int j = tid; j < NROWS; j += 1024) {
        float smv = g_same[j];
        float tt  = g_tot[j];
        float num = smv - 1.0f;                 // remove diagonal (dist_jj = 1.0)
        float den = fmaxf(tt - smv, 1e-10f);
        float frac = num / (num + den);
        if (frac >= 1e-10f) local += logf(frac);
    }
#pragma unroll
    for (int o = 16; o; o >>= 1) local += __shfl_xor_sync(0xffffffffu, local, o);
    __shared__ float ws[32];
    if ((tid & 31) == 0) ws[tid >> 5] = local;
    __syncthreads();
    if (tid < 32) {
        float v = ws[tid];
#pragma unroll
        for (int o = 16; o; o >>= 1) v += __shfl_xor_sync(0xffffffffu, v, o);
        if (tid == 0) out[0] = -v / (float)NROWS;
    }
}

extern "C" void kernel_launch(void* const* d_in, const int* in_sizes, int n_in,
                              void* d_out, int out_size) {
    const float* pred   = (const float*)d_in[0];
    const void*  target = d_in[1];
    const float* temp   = (const float*)d_in[2];

    cudaFuncSetAttribute(tile_kernel, cudaFuncAttributeMaxDynamicSharedMemorySize, SMEM_BYTES);

    detect_kernel<<<1, 128>>>(target);
    prep_kernel<<<NROWS / 16, 512>>>(pred, target);
    dim3 grid(NROWS / BN, NROWS / BM);   // 64x64, upper triangle active
    tile_kernel<<<grid, 256, SMEM_BYTES>>>(pred, temp);
    loss_kernel<<<1, 1024>>>((float*)d_out);
}

// round 10
// speedup vs baseline: 4.5796x; 2.2043x over previous
#include <cuda_runtime.h>
#include <cuda_bf16.h>
#include <cstdint>

// FewShotNCALoss via bf16 mma.sync.m16n8k16 triangle Gram + fused loss.
//   S_tot[j] = sum_i dist_ij, S_same[j] = sum_{t_i==t_j} dist_ij
//   num_j = S_same[j] - 1.0 (diagonal), den_j = max(S_tot-S_same, eps)

#define NROWS 8192
#define DIM   256
#define NCLS  64

#define BM 128
#define BN 128
#define BK 64
#define NKC (DIM / BK)          // 4 k-chunks
#define RSTRIDE 144             // smem row stride bytes (64 bf16 = 128B + 16 pad)
#define TILE_BYTES (BM * RSTRIDE)      // 18432
#define STAGE_BYTES (2 * TILE_BYTES)   // 36864 (A + B)
#define OFF_AUX (2 * STAGE_BYTES)      // 73728
#define SMEM_BYTES (OFF_AUX + 1024 * 4)  // 77824

#define NTILE (NROWS / BM)      // 64
#define TOTAL_CTAS (NTILE * NTILE)

__device__ float g_sq[NROWS];
__device__ float g_tot[NROWS];
__device__ float g_same[NROWS];
__device__ int   g_cls[NROWS];
__device__ __nv_bfloat16 g_bf[(size_t)NROWS * DIM];   // 4MB scratch (static, allowed)
__device__ unsigned g_ctr = 0;

__device__ __forceinline__ uint32_t smem_u32(const void* p) {
    uint32_t a;
    asm("{ .reg .u64 t; cvta.to.shared.u64 t, %1; cvt.u32.u64 %0, t; }" : "=r"(a) : "l"(p));
    return a;
}
__device__ __forceinline__ float fast_exp2(float x) {
    float y; asm("ex2.approx.ftz.f32 %0, %1;" : "=f"(y) : "f"(x)); return y;
}
__device__ __forceinline__ void cp16(uint32_t dst, const void* src) {
    asm volatile("cp.async.cg.shared.global [%0], [%1], 16;" :: "r"(dst), "l"(src) : "memory");
}
#define CP_COMMIT()  asm volatile("cp.async.commit_group;" ::: "memory")
#define CP_WAIT(n)   asm volatile("cp.async.wait_group %0;" :: "n"(n) : "memory")

__device__ __forceinline__ void ldsm4(uint32_t* r, uint32_t addr) {
    asm volatile("ldmatrix.sync.aligned.m8n8.x4.shared.b16 {%0,%1,%2,%3}, [%4];"
                 : "=r"(r[0]), "=r"(r[1]), "=r"(r[2]), "=r"(r[3]) : "r"(addr));
}
__device__ __forceinline__ void mma_bf16(float* c, const uint32_t* a, const uint32_t* b) {
    asm volatile(
        "mma.sync.aligned.m16n8k16.row.col.f32.bf16.bf16.f32 "
        "{%0,%1,%2,%3}, {%4,%5,%6,%7}, {%8,%9}, {%0,%1,%2,%3};"
        : "+f"(c[0]), "+f"(c[1]), "+f"(c[2]), "+f"(c[3])
        : "r"(a[0]), "r"(a[1]), "r"(a[2]), "r"(a[3]), "r"(b[0]), "r"(b[1]));
}
__device__ __forceinline__ float shx(float v, int m) {
    return __shfl_xor_sync(0xffffffffu, v, m);
}

// -------------------- prep: sq norms, bf16 copy, labels, zeroing --------------------
__global__ void prep_kernel(const float* __restrict__ pred, const void* __restrict__ target) {
    int warp = (blockIdx.x * blockDim.x + threadIdx.x) >> 5;
    int lane = threadIdx.x & 31;
    if (warp >= NROWS) return;

    // per-warp int64/int32 detection over first 128 labels (identical result all warps)
    const long long* t64 = (const long long*)target;
    bool ok = true;
#pragma unroll
    for (int q = 0; q < 4; q++) {
        long long v = t64[lane * 4 + q];
        ok = ok && (v >= 0 && v < NCLS);
    }
    unsigned is64 = __all_sync(0xffffffffu, ok);

    const float4* r4 = (const float4*)(pred + (size_t)warp * DIM);
    float4 a = r4[lane], b = r4[lane + 32];

    __nv_bfloat162 p0 = __floats2bfloat162_rn(a.x, a.y);
    __nv_bfloat162 p1 = __floats2bfloat162_rn(a.z, a.w);
    __nv_bfloat162 p2 = __floats2bfloat162_rn(b.x, b.y);
    __nv_bfloat162 p3 = __floats2bfloat162_rn(b.z, b.w);
    uint2 w0 = make_uint2(*(uint32_t*)&p0, *(uint32_t*)&p1);
    uint2 w1 = make_uint2(*(uint32_t*)&p2, *(uint32_t*)&p3);
    *(uint2*)(g_bf + (size_t)warp * DIM + 4 * lane)       = w0;
    *(uint2*)(g_bf + (size_t)warp * DIM + 128 + 4 * lane) = w1;

    float s = a.x*a.x + a.y*a.y + a.z*a.z + a.w*a.w
            + b.x*b.x + b.y*b.y + b.z*b.z + b.w*b.w;
#pragma unroll
    for (int o = 16; o; o >>= 1) s += __shfl_xor_sync(0xffffffffu, s, o);
    if (lane == 0) {
        g_sq[warp] = s;
        g_tot[warp] = 0.f;
        g_same[warp] = 0.f;
        g_cls[warp] = is64 ? (int)((const long long*)target)[warp]
                           : ((const int*)target)[warp];
    }
}

// -------------------- fused loss (runs in the last CTA) --------------------
__device__ __forceinline__ void do_loss(float* out, int tid) {
    __shared__ float ws[8];
    float local = 0.f;
    for (int j = tid; j < NROWS; j += 256) {
        float smv = __ldcg(&g_same[j]);
        float tt  = __ldcg(&g_tot[j]);
        float num = smv - 1.0f;                 // remove diagonal (dist_jj = 1.0)
        float den = fmaxf(tt - smv, 1e-10f);
        float frac = num / (num + den);
        if (frac >= 1e-10f) local += logf(frac);
    }
#pragma unroll
    for (int o = 16; o; o >>= 1) local += __shfl_xor_sync(0xffffffffu, local, o);
    if ((tid & 31) == 0) ws[tid >> 5] = local;
    __syncthreads();
    if (tid == 0) {
        float v = 0.f;
#pragma unroll
        for (int w = 0; w < 8; w++) v += ws[w];
        out[0] = -v / (float)NROWS;
    }
}

// -------------------- main tile kernel --------------------
__global__ __launch_bounds__(256, 2)
void tile_kernel(const float* __restrict__ temp_ptr, float* __restrict__ out) {
    extern __shared__ char smem[];
    const uint32_t sbase = smem_u32(smem);
    const int tid  = threadIdx.x;
    const int bi = blockIdx.y, bj = blockIdx.x;
    const bool active = (bj >= bi);

    if (active) {
        const int Ibase = bi * BM;
        const int Jbase = bj * BN;
        const int lane = tid & 31;
        const int warp = tid >> 5;
        const int gid  = lane >> 2;
        const int tg   = lane & 3;
        const int m0   = (warp >> 1) * 32;
        const int n0   = (warp & 1) * 64;

        float* aux  = (float*)(smem + OFF_AUX);
        float* sSqI = aux;        float* sSqJ = aux + 128;
        int* sClsI  = (int*)(aux + 256); int* sClsJ = (int*)(aux + 384);
        float* sRT  = aux + 512;  float* sRS  = aux + 640;
        float* sCT  = aux + 768;  float* sCS  = aux + 896;

        if (tid < 128) {
            sSqI[tid]  = g_sq[Ibase + tid];
            sSqJ[tid]  = g_sq[Jbase + tid];
            sClsI[tid] = g_cls[Ibase + tid];
            sClsJ[tid] = g_cls[Jbase + tid];
            sRT[tid] = 0.f; sRS[tid] = 0.f; sCT[tid] = 0.f; sCS[tid] = 0.f;
        }

        // ldmatrix per-thread offsets
        const int rowOffA = (lane & 7) + ((lane >> 3) & 1) * 8;
        const int colOffA = (lane >> 4) * 8;
        const int rowOffB = (lane & 7) + ((lane >> 4) & 1) * 8;
        const int colOffB = ((lane >> 3) & 1) * 8;
        const uint32_t aOff = (uint32_t)(m0 + rowOffA) * RSTRIDE + colOffA * 2;
        const uint32_t bOff = (uint32_t)(n0 + rowOffB) * RSTRIDE + colOffB * 2;

        auto load_stage = [&](int s, int k0) {
            uint32_t st = sbase + s * STAGE_BYTES;
#pragma unroll
            for (int q = 0; q < 8; q++) {
                int idx  = tid + q * 256;       // 0..2047
                int tile = idx >> 10;           // 0 = A, 1 = B
                int r    = (idx >> 3) & 127;
                int ch   = idx & 7;
                uint32_t dst = st + tile * TILE_BYTES + r * RSTRIDE + ch * 16;
                const __nv_bfloat16* src =
                    g_bf + (size_t)((tile ? Jbase : Ibase) + r) * DIM + k0 + ch * 8;
                cp16(dst, src);
            }
            CP_COMMIT();
        };

        float acc[2][8][4];
#pragma unroll
        for (int mi = 0; mi < 2; mi++)
#pragma unroll
            for (int nt = 0; nt < 8; nt++)
#pragma unroll
                for (int ci = 0; ci < 4; ci++) acc[mi][nt][ci] = 0.f;

        load_stage(0, 0);

        for (int c = 0; c < NKC; c++) {
            if (c + 1 < NKC) load_stage((c + 1) & 1, (c + 1) * BK);
            if (c + 1 < NKC) CP_WAIT(1); else CP_WAIT(0);
            __syncthreads();

            uint32_t stA = sbase + (c & 1) * STAGE_BYTES;
            uint32_t stB = stA + TILE_BYTES;
#pragma unroll
            for (int ks = 0; ks < 4; ks++) {
                uint32_t a0[4], a1[4], bt[4];
                uint32_t bfr[8][2];
                ldsm4(a0, stA + aOff + ks * 32);
                ldsm4(a1, stA + aOff + ks * 32 + 16 * RSTRIDE);
#pragma unroll
                for (int pn = 0; pn < 4; pn++) {
                    ldsm4(bt, stB + bOff + ks * 32 + pn * (16 * RSTRIDE));
                    bfr[2 * pn][0] = bt[0]; bfr[2 * pn][1] = bt[1];
                    bfr[2 * pn + 1][0] = bt[2]; bfr[2 * pn + 1][1] = bt[3];
                }
#pragma unroll
                for (int nt = 0; nt < 8; nt++) {
                    mma_bf16(acc[0][nt], a0, bfr[nt]);
                    mma_bf16(acc[1][nt], a1, bfr[nt]);
                }
            }
            __syncthreads();
        }

        // ---- epilogue ----
        const float negsc = -1.4426950408889634f / (*temp_ptr);
        float colT[16], colS[16];
#pragma unroll
        for (int q = 0; q < 16; q++) { colT[q] = 0.f; colS[q] = 0.f; }

#pragma unroll
        for (int mi = 0; mi < 2; mi++) {
            const int mlo = m0 + 16 * mi + gid;
            const float si0 = sSqI[mlo],  si1 = sSqI[mlo + 8];
            const int   ci0 = sClsI[mlo], ci1 = sClsI[mlo + 8];
            float rt0 = 0.f, rs0 = 0.f, rt1 = 0.f, rs1 = 0.f;
#pragma unroll
            for (int nt = 0; nt < 8; nt++) {
#pragma unroll
                for (int p = 0; p < 2; p++) {
                    const int n = n0 + 8 * nt + 2 * tg + p;
                    const float sj = sSqJ[n];
                    const int   cj = sClsJ[n];
                    float p0 = fmaxf(fmaf(-2.f, acc[mi][nt][p],     si0 + sj), 1e-10f);
                    float p1 = fmaxf(fmaf(-2.f, acc[mi][nt][2 + p], si1 + sj), 1e-10f);
                    float d0 = fast_exp2(p0 * negsc);
                    float d1 = fast_exp2(p1 * negsc);
                    rt0 += d0; rt1 += d1;
                    colT[nt * 2 + p] += d0 + d1;
                    float s0 = (ci0 == cj) ? d0 : 0.f;
                    float s1 = (ci1 == cj) ? d1 : 0.f;
                    rs0 += s0; rs1 += s1;
                    colS[nt * 2 + p] += s0 + s1;
                }
            }
            // reduce across tg (4 lanes sharing gid) -> conflict-free atomics
            rt0 += shx(rt0, 1); rt0 += shx(rt0, 2);
            rs0 += shx(rs0, 1); rs0 += shx(rs0, 2);
            rt1 += shx(rt1, 1); rt1 += shx(rt1, 2);
            rs1 += shx(rs1, 1); rs1 += shx(rs1, 2);
            if (tg == 0) {
                atomicAdd(&sRT[mlo], rt0);     atomicAdd(&sRS[mlo], rs0);
                atomicAdd(&sRT[mlo + 8], rt1); atomicAdd(&sRS[mlo + 8], rs1);
            }
        }
        // reduce columns across gid (masks 4,8,16) -> conflict-free atomics
#pragma unroll
        for (int q = 0; q < 16; q++) {
            colT[q] += shx(colT[q], 4); colT[q] += shx(colT[q], 8); colT[q] += shx(colT[q], 16);
            colS[q] += shx(colS[q], 4); colS[q] += shx(colS[q], 8); colS[q] += shx(colS[q], 16);
        }
        if (gid == 0) {
#pragma unroll
            for (int nt = 0; nt < 8; nt++)
#pragma unroll
                for (int p = 0; p < 2; p++) {
                    const int n = n0 + 8 * nt + 2 * tg + p;
                    atomicAdd(&sCT[n], colT[nt * 2 + p]);
                    atomicAdd(&sCS[n], colS[nt * 2 + p]);
                }
        }
        __syncthreads();

        if (tid < 128) {
            atomicAdd(&g_tot[Jbase + tid],  sCT[tid]);
            atomicAdd(&g_same[Jbase + tid], sCS[tid]);
            if (bi != bj) {
                atomicAdd(&g_tot[Ibase + tid],  sRT[tid]);
                atomicAdd(&g_same[Ibase + tid], sRS[tid]);
            }
        }
    }

    // ---- completion counter + fused loss in the last CTA ----
    __shared__ int s_last;
    if (tid == 0) {
        __threadfence();
        unsigned v = atomicAdd(&g_ctr, 1u);
        s_last = (v == TOTAL_CTAS - 1);
    }
    __syncthreads();
    if (s_last) {
        __threadfence();   // acquire side: order counter observation before g_tot/g_same reads
        do_loss(out, tid);
        __syncthreads();
        if (tid == 0) g_ctr = 0;   // reset for next graph replay
    }
}

extern "C" void kernel_launch(void* const* d_in, const int* in_sizes, int n_in,
                              void* d_out, int out_size) {
    const float* pred   = (const float*)d_in[0];
    const void*  target = d_in[1];
    const float* temp   = (const float*)d_in[2];

    cudaFuncSetAttribute(tile_kernel, cudaFuncAttributeMaxDynamicSharedMemorySize, SMEM_BYTES);

    prep_kernel<<<NROWS / 16, 512>>>(pred, target);
    dim3 grid(NTILE, NTILE);   // 64x64, upper triangle active
    tile_kernel<<<grid, 256, SMEM_BYTES>>>(temp, (float*)d_out);
}

// round 11
// speedup vs baseline: 4.8393x; 1.0567x over previous
#include <cuda_runtime.h>
#include <cuda_bf16.h>
#include <cstdint>

// FewShotNCALoss via bf16 mma.sync.m16n8k16 triangle Gram + fused loss.
// 512 threads/CTA, 32x32 warp tiles -> 64 regs/thread -> 2 CTAs/SM (50% occ).

#define NROWS 8192
#define DIM   256
#define NCLS  64

#define BM 128
#define BN 128
#define BK 64
#define NKC (DIM / BK)          // 4 k-chunks
#define RSTRIDE 144             // smem row stride bytes (64 bf16 = 128B + 16 pad)
#define TILE_BYTES (BM * RSTRIDE)      // 18432
#define STAGE_BYTES (2 * TILE_BYTES)   // 36864 (A + B)
#define OFF_AUX (2 * STAGE_BYTES)      // 73728
#define SMEM_BYTES (OFF_AUX + 1024 * 4)  // 77824

#define NTHREADS 512
#define NTILE (NROWS / BM)      // 64
#define TOTAL_CTAS (NTILE * NTILE)

__device__ float g_sq[NROWS];
__device__ float g_tot[NROWS];
__device__ float g_same[NROWS];
__device__ int   g_cls[NROWS];
__device__ __nv_bfloat16 g_bf[(size_t)NROWS * DIM];   // 4MB scratch (static, allowed)
__device__ unsigned g_ctr = 0;

__device__ __forceinline__ uint32_t smem_u32(const void* p) {
    uint32_t a;
    asm("{ .reg .u64 t; cvta.to.shared.u64 t, %1; cvt.u32.u64 %0, t; }" : "=r"(a) : "l"(p));
    return a;
}
__device__ __forceinline__ float fast_exp2(float x) {
    float y; asm("ex2.approx.ftz.f32 %0, %1;" : "=f"(y) : "f"(x)); return y;
}
__device__ __forceinline__ void cp16(uint32_t dst, const void* src) {
    asm volatile("cp.async.cg.shared.global [%0], [%1], 16;" :: "r"(dst), "l"(src) : "memory");
}
#define CP_COMMIT()  asm volatile("cp.async.commit_group;" ::: "memory")
#define CP_WAIT(n)   asm volatile("cp.async.wait_group %0;" :: "n"(n) : "memory")

__device__ __forceinline__ void ldsm4(uint32_t* r, uint32_t addr) {
    asm volatile("ldmatrix.sync.aligned.m8n8.x4.shared.b16 {%0,%1,%2,%3}, [%4];"
                 : "=r"(r[0]), "=r"(r[1]), "=r"(r[2]), "=r"(r[3]) : "r"(addr));
}
__device__ __forceinline__ void mma_bf16(float* c, const uint32_t* a, const uint32_t* b) {
    asm volatile(
        "mma.sync.aligned.m16n8k16.row.col.f32.bf16.bf16.f32 "
        "{%0,%1,%2,%3}, {%4,%5,%6,%7}, {%8,%9}, {%0,%1,%2,%3};"
        : "+f"(c[0]), "+f"(c[1]), "+f"(c[2]), "+f"(c[3])
        : "r"(a[0]), "r"(a[1]), "r"(a[2]), "r"(a[3]), "r"(b[0]), "r"(b[1]));
}
__device__ __forceinline__ float shx(float v, int m) {
    return __shfl_xor_sync(0xffffffffu, v, m);
}

// -------------------- prep: sq norms, bf16 copy, labels, zeroing --------------------
__global__ void prep_kernel(const float* __restrict__ pred, const void* __restrict__ target) {
    int warp = (blockIdx.x * blockDim.x + threadIdx.x) >> 5;
    int lane = threadIdx.x & 31;
    if (warp >= NROWS) return;

    const long long* t64 = (const long long*)target;
    bool ok = true;
#pragma unroll
    for (int q = 0; q < 4; q++) {
        long long v = t64[lane * 4 + q];
        ok = ok && (v >= 0 && v < NCLS);
    }
    unsigned is64 = __all_sync(0xffffffffu, ok);

    const float4* r4 = (const float4*)(pred + (size_t)warp * DIM);
    float4 a = r4[lane], b = r4[lane + 32];

    __nv_bfloat162 p0 = __floats2bfloat162_rn(a.x, a.y);
    __nv_bfloat162 p1 = __floats2bfloat162_rn(a.z, a.w);
    __nv_bfloat162 p2 = __floats2bfloat162_rn(b.x, b.y);
    __nv_bfloat162 p3 = __floats2bfloat162_rn(b.z, b.w);
    uint2 w0 = make_uint2(*(uint32_t*)&p0, *(uint32_t*)&p1);
    uint2 w1 = make_uint2(*(uint32_t*)&p2, *(uint32_t*)&p3);
    *(uint2*)(g_bf + (size_t)warp * DIM + 4 * lane)       = w0;
    *(uint2*)(g_bf + (size_t)warp * DIM + 128 + 4 * lane) = w1;

    float s = a.x*a.x + a.y*a.y + a.z*a.z + a.w*a.w
            + b.x*b.x + b.y*b.y + b.z*b.z + b.w*b.w;
#pragma unroll
    for (int o = 16; o; o >>= 1) s += __shfl_xor_sync(0xffffffffu, s, o);
    if (lane == 0) {
        g_sq[warp] = s;
        g_tot[warp] = 0.f;
        g_same[warp] = 0.f;
        g_cls[warp] = is64 ? (int)((const long long*)target)[warp]
                           : ((const int*)target)[warp];
    }
}

// -------------------- fused loss (runs in the last CTA, 512 threads) --------------------
__device__ __forceinline__ void do_loss(float* out, int tid) {
    __shared__ float ws[16];
    float local = 0.f;
    for (int j = tid; j < NROWS; j += NTHREADS) {
        float smv = __ldcg(&g_same[j]);
        float tt  = __ldcg(&g_tot[j]);
        float num = smv - 1.0f;                 // remove diagonal (dist_jj = 1.0)
        float den = fmaxf(tt - smv, 1e-10f);
        float frac = num / (num + den);
        if (frac >= 1e-10f) local += logf(frac);
    }
#pragma unroll
    for (int o = 16; o; o >>= 1) local += __shfl_xor_sync(0xffffffffu, local, o);
    if ((tid & 31) == 0) ws[tid >> 5] = local;
    __syncthreads();
    if (tid == 0) {
        float v = 0.f;
#pragma unroll
        for (int w = 0; w < 16; w++) v += ws[w];
        out[0] = -v / (float)NROWS;
    }
}

// -------------------- main tile kernel --------------------
__global__ __launch_bounds__(NTHREADS, 2)
void tile_kernel(const float* __restrict__ temp_ptr, float* __restrict__ out) {
    extern __shared__ char smem[];
    const uint32_t sbase = smem_u32(smem);
    const int tid  = threadIdx.x;
    const int bi = blockIdx.y, bj = blockIdx.x;
    const bool active = (bj >= bi);

    if (active) {
        const int Ibase = bi * BM;
        const int Jbase = bj * BN;
        const int lane = tid & 31;
        const int warp = tid >> 5;            // 0..15
        const int gid  = lane >> 2;
        const int tg   = lane & 3;
        const int m0   = (warp >> 2) * 32;    // 4 row-bands of 32
        const int n0   = (warp & 3) * 32;     // 4 col-bands of 32

        float* aux  = (float*)(smem + OFF_AUX);
        float* sSqI = aux;        float* sSqJ = aux + 128;
        int* sClsI  = (int*)(aux + 256); int* sClsJ = (int*)(aux + 384);
        float* sRT  = aux + 512;  float* sRS  = aux + 640;
        float* sCT  = aux + 768;  float* sCS  = aux + 896;

        if (tid < 128) {
            sSqI[tid]  = g_sq[Ibase + tid];
            sSqJ[tid]  = g_sq[Jbase + tid];
            sClsI[tid] = g_cls[Ibase + tid];
            sClsJ[tid] = g_cls[Jbase + tid];
            sRT[tid] = 0.f; sRS[tid] = 0.f; sCT[tid] = 0.f; sCS[tid] = 0.f;
        }

        // ldmatrix per-thread offsets (same maps as validated R10 kernel)
        const int rowOffA = (lane & 7) + ((lane >> 3) & 1) * 8;
        const int colOffA = (lane >> 4) * 8;
        const int rowOffB = (lane & 7) + ((lane >> 4) & 1) * 8;
        const int colOffB = ((lane >> 3) & 1) * 8;
        const uint32_t aOff = (uint32_t)(m0 + rowOffA) * RSTRIDE + colOffA * 2;
        const uint32_t bOff = (uint32_t)(n0 + rowOffB) * RSTRIDE + colOffB * 2;

        auto load_stage = [&](int s, int k0) {
            uint32_t st = sbase + s * STAGE_BYTES;
#pragma unroll
            for (int q = 0; q < 4; q++) {
                int idx  = tid + q * NTHREADS;  // 0..2047
                int tile = idx >> 10;           // 0 = A, 1 = B
                int r    = (idx >> 3) & 127;
                int ch   = idx & 7;
                uint32_t dst = st + tile * TILE_BYTES + r * RSTRIDE + ch * 16;
                const __nv_bfloat16* src =
                    g_bf + (size_t)((tile ? Jbase : Ibase) + r) * DIM + k0 + ch * 8;
                cp16(dst, src);
            }
            CP_COMMIT();
        };

        float acc[2][4][4];
#pragma unroll
        for (int mi = 0; mi < 2; mi++)
#pragma unroll
            for (int nt = 0; nt < 4; nt++)
#pragma unroll
                for (int ci = 0; ci < 4; ci++) acc[mi][nt][ci] = 0.f;

        load_stage(0, 0);

        for (int c = 0; c < NKC; c++) {
            if (c + 1 < NKC) load_stage((c + 1) & 1, (c + 1) * BK);
            if (c + 1 < NKC) CP_WAIT(1); else CP_WAIT(0);
            __syncthreads();

            uint32_t stA = sbase + (c & 1) * STAGE_BYTES;
            uint32_t stB = stA + TILE_BYTES;
#pragma unroll
            for (int ks = 0; ks < 4; ks++) {
                uint32_t a0[4], a1[4], bt[4];
                uint32_t bfr[4][2];
                ldsm4(a0, stA + aOff + ks * 32);
                ldsm4(a1, stA + aOff + ks * 32 + 16 * RSTRIDE);
#pragma unroll
                for (int pn = 0; pn < 2; pn++) {
                    ldsm4(bt, stB + bOff + ks * 32 + pn * (16 * RSTRIDE));
                    bfr[2 * pn][0] = bt[0]; bfr[2 * pn][1] = bt[1];
                    bfr[2 * pn + 1][0] = bt[2]; bfr[2 * pn + 1][1] = bt[3];
                }
#pragma unroll
                for (int nt = 0; nt < 4; nt++) {
                    mma_bf16(acc[0][nt], a0, bfr[nt]);
                    mma_bf16(acc[1][nt], a1, bfr[nt]);
                }
            }
            __syncthreads();
        }

        // ---- epilogue ----
        const float negsc = -1.4426950408889634f / (*temp_ptr);
        float colT[8], colS[8];
#pragma unroll
        for (int q = 0; q < 8; q++) { colT[q] = 0.f; colS[q] = 0.f; }

#pragma unroll
        for (int mi = 0; mi < 2; mi++) {
            const int mlo = m0 + 16 * mi + gid;
            const float si0 = sSqI[mlo],  si1 = sSqI[mlo + 8];
            const int   ci0 = sClsI[mlo], ci1 = sClsI[mlo + 8];
            float rt0 = 0.f, rs0 = 0.f, rt1 = 0.f, rs1 = 0.f;
#pragma unroll
            for (int nt = 0; nt < 4; nt++) {
#pragma unroll
                for (int p = 0; p < 2; p++) {
                    const int n = n0 + 8 * nt + 2 * tg + p;
                    const float sj = sSqJ[n];
                    const int   cj = sClsJ[n];
                    float p0 = fmaxf(fmaf(-2.f, acc[mi][nt][p],     si0 + sj), 1e-10f);
                    float p1 = fmaxf(fmaf(-2.f, acc[mi][nt][2 + p], si1 + sj), 1e-10f);
                    float d0 = fast_exp2(p0 * negsc);
                    float d1 = fast_exp2(p1 * negsc);
                    rt0 += d0; rt1 += d1;
                    colT[nt * 2 + p] += d0 + d1;
                    float s0 = (ci0 == cj) ? d0 : 0.f;
                    float s1 = (ci1 == cj) ? d1 : 0.f;
                    rs0 += s0; rs1 += s1;
                    colS[nt * 2 + p] += s0 + s1;
                }
            }
            // reduce across tg (4 lanes sharing gid) -> conflict-free atomics
            rt0 += shx(rt0, 1); rt0 += shx(rt0, 2);
            rs0 += shx(rs0, 1); rs0 += shx(rs0, 2);
            rt1 += shx(rt1, 1); rt1 += shx(rt1, 2);
            rs1 += shx(rs1, 1); rs1 += shx(rs1, 2);
            if (tg == 0) {
                atomicAdd(&sRT[mlo], rt0);     atomicAdd(&sRS[mlo], rs0);
                atomicAdd(&sRT[mlo + 8], rt1); atomicAdd(&sRS[mlo + 8], rs1);
            }
        }
        // reduce columns across gid (masks 4,8,16) -> conflict-free atomics
#pragma unroll
        for (int q = 0; q < 8; q++) {
            colT[q] += shx(colT[q], 4); colT[q] += shx(colT[q], 8); colT[q] += shx(colT[q], 16);
            colS[q] += shx(colS[q], 4); colS[q] += shx(colS[q], 8); colS[q] += shx(colS[q], 16);
        }
        if (gid == 0) {
#pragma unroll
            for (int nt = 0; nt < 4; nt++)
#pragma unroll
                for (int p = 0; p < 2; p++) {
                    const int n = n0 + 8 * nt + 2 * tg + p;
                    atomicAdd(&sCT[n], colT[nt * 2 + p]);
                    atomicAdd(&sCS[n], colS[nt * 2 + p]);
                }
        }
        __syncthreads();

        if (tid < 128) {
            atomicAdd(&g_tot[Jbase + tid],  sCT[tid]);
            atomicAdd(&g_same[Jbase + tid], sCS[tid]);
            if (bi != bj) {
                atomicAdd(&g_tot[Ibase + tid],  sRT[tid]);
                atomicAdd(&g_same[Ibase + tid], sRS[tid]);
            }
        }
    }

    // ---- completion counter + fused loss in the last CTA ----
    __shared__ int s_last;
    if (tid == 0) {
        __threadfence();
        unsigned v = atomicAdd(&g_ctr, 1u);
        s_last = (v == TOTAL_CTAS - 1);
    }
    __syncthreads();
    if (s_last) {
        __threadfence();   // acquire: order counter observation before g_tot/g_same reads
        do_loss(out, tid);
        __syncthreads();
        if (tid == 0) g_ctr = 0;   // reset for next graph replay
    }
}

extern "C" void kernel_launch(void* const* d_in, const int* in_sizes, int n_in,
                              void* d_out, int out_size) {
    const float* pred   = (const float*)d_in[0];
    const void*  target = d_in[1];
    const float* temp   = (const float*)d_in[2];

    cudaFuncSetAttribute(tile_kernel, cudaFuncAttributeMaxDynamicSharedMemorySize, SMEM_BYTES);

    prep_kernel<<<NROWS / 16, 512>>>(pred, target);
    dim3 grid(NTILE, NTILE);   // 64x64, upper triangle active
    tile_kernel<<<grid, NTHREADS, SMEM_BYTES>>>(temp, (float*)d_out);
}

// round 12
// speedup vs baseline: 5.1653x; 1.0674x over previous
#include <cuda_runtime.h>
#include <cuda_bf16.h>
#include <cstdint>

// FewShotNCALoss via bf16 mma.sync.m16n8k16 triangle Gram + fused loss.
// Loads via cp.async.bulk (2 instrs/stage instead of 2304 LDGSTS) from a
// pre-swizzled, K-plane-major bf16 copy of pred.

#define NROWS 8192
#define DIM   256
#define NCLS  64

#define BM 128
#define BN 128
#define BK 64                   // one K-plane (64 bf16 = 128B per row)
#define NKC (DIM / BK)          // 4 chunks / planes
#define PLANE_ELEMS ((size_t)NROWS * 64)     // bf16 per plane
#define PLANE_BYTES ((size_t)NROWS * 128)

#define CHUNK_BYTES 16384       // 128 rows x 128B, contiguous in a plane
#define STAGE_BYTES 32768       // A chunk + B chunk
#define OFF_AUX   65536         // after 2 stages
#define OFF_MBAR  (OFF_AUX + 4096)
#define SMEM_BYTES (OFF_MBAR + 128)

#define NTHREADS 512
#define NTILE (NROWS / BM)      // 64
#define TOTAL_CTAS (NTILE * NTILE)

__device__ float g_sq[NROWS];
__device__ float g_tot[NROWS];
__device__ float g_same[NROWS];
__device__ int   g_cls[NROWS];
__device__ __nv_bfloat16 g_bf[4 * PLANE_ELEMS];   // 4MB, K-plane major, SW128-preswizzled
__device__ unsigned g_ctr = 0;

__device__ __forceinline__ uint32_t smem_u32(const void* p) {
    uint32_t a;
    asm("{ .reg .u64 t; cvta.to.shared.u64 t, %1; cvt.u32.u64 %0, t; }" : "=r"(a) : "l"(p));
    return a;
}
__device__ __forceinline__ float fast_exp2(float x) {
    float y; asm("ex2.approx.ftz.f32 %0, %1;" : "=f"(y) : "f"(x)); return y;
}
__device__ __forceinline__ void ldsm4(uint32_t* r, uint32_t addr) {
    asm volatile("ldmatrix.sync.aligned.m8n8.x4.shared.b16 {%0,%1,%2,%3}, [%4];"
                 : "=r"(r[0]), "=r"(r[1]), "=r"(r[2]), "=r"(r[3]) : "r"(addr));
}
__device__ __forceinline__ void mma_bf16(float* c, const uint32_t* a, const uint32_t* b) {
    asm volatile(
        "mma.sync.aligned.m16n8k16.row.col.f32.bf16.bf16.f32 "
        "{%0,%1,%2,%3}, {%4,%5,%6,%7}, {%8,%9}, {%0,%1,%2,%3};"
        : "+f"(c[0]), "+f"(c[1]), "+f"(c[2]), "+f"(c[3])
        : "r"(a[0]), "r"(a[1]), "r"(a[2]), "r"(a[3]), "r"(b[0]), "r"(b[1]));
}
__device__ __forceinline__ float shx(float v, int m) {
    return __shfl_xor_sync(0xffffffffu, v, m);
}
__device__ __forceinline__ void bulk_ld(uint32_t dst, const void* src, uint32_t bytes, uint32_t mbar) {
    asm volatile(
        "cp.async.bulk.shared::cluster.global.mbarrier::complete_tx::bytes [%0], [%1], %2, [%3];"
        :: "r"(dst), "l"(src), "r"(bytes), "r"(mbar) : "memory");
}
__device__ __forceinline__ void mbar_init(uint32_t mbar, uint32_t cnt) {
    asm volatile("mbarrier.init.shared.b64 [%0], %1;" :: "r"(mbar), "r"(cnt) : "memory");
}
__device__ __forceinline__ void mbar_expect(uint32_t mbar, uint32_t tx) {
    asm volatile("mbarrier.arrive.expect_tx.shared.b64 _, [%0], %1;" :: "r"(mbar), "r"(tx) : "memory");
}
__device__ __forceinline__ void mbar_wait(uint32_t mbar, uint32_t parity) {
    asm volatile(
        "{\n\t.reg .pred P;\n\t"
        "W%=:\n\t"
        "mbarrier.try_wait.parity.acquire.cta.shared::cta.b64 P, [%0], %1, 0x989680;\n\t"
        "@P bra.uni D%=;\n\t"
        "bra.uni W%=;\n\t"
        "D%=:\n\t}"
        :: "r"(mbar), "r"(parity) : "memory");
}

// -------------------- prep: sq norms, pre-swizzled plane-major bf16, labels --------------------
__global__ void prep_kernel(const float* __restrict__ pred, const void* __restrict__ target) {
    int warp = (blockIdx.x * blockDim.x + threadIdx.x) >> 5;
    int lane = threadIdx.x & 31;
    if (warp >= NROWS) return;

    const long long* t64 = (const long long*)target;
    bool ok = true;
#pragma unroll
    for (int q = 0; q < 4; q++) {
        long long v = t64[lane * 4 + q];
        ok = ok && (v >= 0 && v < NCLS);
    }
    unsigned is64 = __all_sync(0xffffffffu, ok);

    const float4* r4 = (const float4*)(pred + (size_t)warp * DIM);
    float4 a = r4[lane], b = r4[lane + 32];

    __nv_bfloat162 p0 = __floats2bfloat162_rn(a.x, a.y);
    __nv_bfloat162 p1 = __floats2bfloat162_rn(a.z, a.w);
    __nv_bfloat162 p2 = __floats2bfloat162_rn(b.x, b.y);
    __nv_bfloat162 p3 = __floats2bfloat162_rn(b.z, b.w);
    uint2 wa = make_uint2(*(uint32_t*)&p0, *(uint32_t*)&p1);   // cols 4l..4l+3   of first 128
    uint2 wb = make_uint2(*(uint32_t*)&p2, *(uint32_t*)&p3);   // cols 128+4l..   of second 128

    // plane = col/64; within-plane byte col cb = (col%64)*2 = 8*(lane&15); SW128 pre-swizzle:
    // swizzled cb = cb ^ ((row&7)<<4)
    uint32_t cb  = 8u * (lane & 15);
    uint32_t cbs = cb ^ ((warp & 7u) << 4);
    int planeA = (lane >> 4);          // 0 or 1
    int planeB = 2 + (lane >> 4);      // 2 or 3
    char* base = (char*)g_bf;
    *(uint2*)(base + planeA * PLANE_BYTES + (size_t)warp * 128 + cbs) = wa;
    *(uint2*)(base + planeB * PLANE_BYTES + (size_t)warp * 128 + cbs) = wb;

    float s = a.x*a.x + a.y*a.y + a.z*a.z + a.w*a.w
            + b.x*b.x + b.y*b.y + b.z*b.z + b.w*b.w;
#pragma unroll
    for (int o = 16; o; o >>= 1) s += __shfl_xor_sync(0xffffffffu, s, o);
    if (lane == 0) {
        g_sq[warp] = s;
        g_tot[warp] = 0.f;
        g_same[warp] = 0.f;
        g_cls[warp] = is64 ? (int)((const long long*)target)[warp]
                           : ((const int*)target)[warp];
    }
}

// -------------------- fused loss (runs in the last CTA) --------------------
__device__ __forceinline__ void do_loss(float* out, int tid) {
    __shared__ float ws[16];
    float local = 0.f;
    for (int j = tid; j < NROWS; j += NTHREADS) {
        float smv = __ldcg(&g_same[j]);
        float tt  = __ldcg(&g_tot[j]);
        float num = smv - 1.0f;                 // remove diagonal (dist_jj = 1.0)
        float den = fmaxf(tt - smv, 1e-10f);
        float frac = num / (num + den);
        if (frac >= 1e-10f) local += logf(frac);
    }
#pragma unroll
    for (int o = 16; o; o >>= 1) local += __shfl_xor_sync(0xffffffffu, local, o);
    if ((tid & 31) == 0) ws[tid >> 5] = local;
    __syncthreads();
    if (tid == 0) {
        float v = 0.f;
#pragma unroll
        for (int w = 0; w < 16; w++) v += ws[w];
        out[0] = -v / (float)NROWS;
    }
}

// -------------------- main tile kernel --------------------
__global__ __launch_bounds__(NTHREADS, 2)
void tile_kernel(const float* __restrict__ temp_ptr, float* __restrict__ out) {
    extern __shared__ char smem[];
    const uint32_t sbase = smem_u32(smem);
    const int tid  = threadIdx.x;
    const int bi = blockIdx.y, bj = blockIdx.x;
    const bool active = (bj >= bi);

    if (active) {
        const int Ibase = bi * BM;
        const int Jbase = bj * BN;
        const int lane = tid & 31;
        const int warp = tid >> 5;            // 0..15
        const int gid  = lane >> 2;
        const int tg   = lane & 3;
        const int m0   = (warp >> 2) * 32;
        const int n0   = (warp & 3) * 32;

        float* aux  = (float*)(smem + OFF_AUX);
        float* sSqI = aux;        float* sSqJ = aux + 128;
        int* sClsI  = (int*)(aux + 256); int* sClsJ = (int*)(aux + 384);
        float* sRT  = aux + 512;  float* sRS  = aux + 640;
        float* sCT  = aux + 768;  float* sCS  = aux + 896;
        const uint32_t mb0 = sbase + OFF_MBAR;
        const uint32_t mb1 = mb0 + 8;

        if (tid < 128) {
            sSqI[tid]  = g_sq[Ibase + tid];
            sSqJ[tid]  = g_sq[Jbase + tid];
            sClsI[tid] = g_cls[Ibase + tid];
            sClsJ[tid] = g_cls[Jbase + tid];
            sRT[tid] = 0.f; sRS[tid] = 0.f; sCT[tid] = 0.f; sCS[tid] = 0.f;
        }
        if (tid == 0) { mbar_init(mb0, 1); mbar_init(mb1, 1); }
        __syncthreads();

        // ldmatrix lane offsets (maps validated in R10/R11); swizzle replaces pad
        const int rowA = m0 + (lane & 7) + ((lane >> 3) & 1) * 8;
        const int cuA  = (lane >> 4);                       // 16B-unit 0/1
        const int rowB = n0 + (lane & 7) + ((lane >> 4) & 1) * 8;
        const int cuB  = ((lane >> 3) & 1);
        const uint32_t rsA = (uint32_t)rowA & 7, rsB = (uint32_t)rowB & 7;

        const char* gbase = (const char*)g_bf;
        auto issue = [&](int c) {            // tid 0 only
            uint32_t st = sbase + (c & 1) * STAGE_BYTES;
            uint32_t mb = (c & 1) ? mb1 : mb0;
            mbar_expect(mb, STAGE_BYTES);
            bulk_ld(st,               gbase + c * PLANE_BYTES + (size_t)Ibase * 128, CHUNK_BYTES, mb);
            bulk_ld(st + CHUNK_BYTES, gbase + c * PLANE_BYTES + (size_t)Jbase * 128, CHUNK_BYTES, mb);
        };

        float acc[2][4][4];
#pragma unroll
        for (int mi = 0; mi < 2; mi++)
#pragma unroll
            for (int nt = 0; nt < 4; nt++)
#pragma unroll
                for (int ci = 0; ci < 4; ci++) acc[mi][nt][ci] = 0.f;

        if (tid == 0) { issue(0); issue(1); }

        for (int c = 0; c < NKC; c++) {
            mbar_wait((c & 1) ? mb1 : mb0, (c >> 1) & 1);

            uint32_t stA = sbase + (c & 1) * STAGE_BYTES;
            uint32_t stB = stA + CHUNK_BYTES;
#pragma unroll
            for (int ks = 0; ks < 4; ks++) {
                uint32_t a0[4], a1[4], bt[4];
                uint32_t bfr[4][2];
                ldsm4(a0, stA + rowA * 128        + ((((uint32_t)(ks * 2) + cuA) ^ rsA) << 4));
                ldsm4(a1, stA + (rowA + 16) * 128 + ((((uint32_t)(ks * 2) + cuA) ^ rsA) << 4));
#pragma unroll
                for (int pn = 0; pn < 2; pn++) {
                    ldsm4(bt, stB + (rowB + 16 * pn) * 128 + ((((uint32_t)(ks * 2) + cuB) ^ rsB) << 4));
                    bfr[2 * pn][0] = bt[0]; bfr[2 * pn][1] = bt[1];
                    bfr[2 * pn + 1][0] = bt[2]; bfr[2 * pn + 1][1] = bt[3];
                }
#pragma unroll
                for (int nt = 0; nt < 4; nt++) {
                    mma_bf16(acc[0][nt], a0, bfr[nt]);
                    mma_bf16(acc[1][nt], a1, bfr[nt]);
                }
            }
            __syncthreads();                       // stage fully consumed
            if (c + 2 < NKC && tid == 0) issue(c + 2);
        }

        // ---- epilogue ----
        const float negsc = -1.4426950408889634f / (*temp_ptr);
        float colT[8], colS[8];
#pragma unroll
        for (int q = 0; q < 8; q++) { colT[q] = 0.f; colS[q] = 0.f; }

#pragma unroll
        for (int mi = 0; mi < 2; mi++) {
            const int mlo = m0 + 16 * mi + gid;
            const float si0 = sSqI[mlo],  si1 = sSqI[mlo + 8];
            const int   ci0 = sClsI[mlo], ci1 = sClsI[mlo + 8];
            float rt0 = 0.f, rs0 = 0.f, rt1 = 0.f, rs1 = 0.f;
#pragma unroll
            for (int nt = 0; nt < 4; nt++) {
#pragma unroll
                for (int p = 0; p < 2; p++) {
                    const int n = n0 + 8 * nt + 2 * tg + p;
                    const float sj = sSqJ[n];
                    const int   cj = sClsJ[n];
                    float p0 = fmaxf(fmaf(-2.f, acc[mi][nt][p],     si0 + sj), 1e-10f);
                    float p1 = fmaxf(fmaf(-2.f, acc[mi][nt][2 + p], si1 + sj), 1e-10f);
                    float d0 = fast_exp2(p0 * negsc);
                    float d1 = fast_exp2(p1 * negsc);
                    rt0 += d0; rt1 += d1;
                    colT[nt * 2 + p] += d0 + d1;
                    float s0 = (ci0 == cj) ? d0 : 0.f;
                    float s1 = (ci1 == cj) ? d1 : 0.f;
                    rs0 += s0; rs1 += s1;
                    colS[nt * 2 + p] += s0 + s1;
                }
            }
            rt0 += shx(rt0, 1); rt0 += shx(rt0, 2);
            rs0 += shx(rs0, 1); rs0 += shx(rs0, 2);
            rt1 += shx(rt1, 1); rt1 += shx(rt1, 2);
            rs1 += shx(rs1, 1); rs1 += shx(rs1, 2);
            if (tg == 0) {
                atomicAdd(&sRT[mlo], rt0);     atomicAdd(&sRS[mlo], rs0);
                atomicAdd(&sRT[mlo + 8], rt1); atomicAdd(&sRS[mlo + 8], rs1);
            }
        }
#pragma unroll
        for (int q = 0; q < 8; q++) {
            colT[q] += shx(colT[q], 4); colT[q] += shx(colT[q], 8); colT[q] += shx(colT[q], 16);
            colS[q] += shx(colS[q], 4); colS[q] += shx(colS[q], 8); colS[q] += shx(colS[q], 16);
        }
        if (gid == 0) {
#pragma unroll
            for (int nt = 0; nt < 4; nt++)
#pragma unroll
                for (int p = 0; p < 2; p++) {
                    const int n = n0 + 8 * nt + 2 * tg + p;
                    atomicAdd(&sCT[n], colT[nt * 2 + p]);
                    atomicAdd(&sCS[n], colS[nt * 2 + p]);
                }
        }
        __syncthreads();

        if (tid < 128) {
            atomicAdd(&g_tot[Jbase + tid],  sCT[tid]);
            atomicAdd(&g_same[Jbase + tid], sCS[tid]);
            if (bi != bj) {
                atomicAdd(&g_tot[Ibase + tid],  sRT[tid]);
                atomicAdd(&g_same[Ibase + tid], sRS[tid]);
            }
        }
    }

    // ---- completion counter + fused loss in the last CTA ----
    __shared__ int s_last;
    if (tid == 0) {
        __threadfence();
        unsigned v = atomicAdd(&g_ctr, 1u);
        s_last = (v == TOTAL_CTAS - 1);
    }
    __syncthreads();
    if (s_last) {
        __threadfence();   // acquire: order counter observation before g_tot/g_same reads
        do_loss(out, tid);
        __syncthreads();
        if (tid == 0) g_ctr = 0;   // reset for next graph replay
    }
}

extern "C" void kernel_launch(void* const* d_in, const int* in_sizes, int n_in,
                              void* d_out, int out_size) {
    const float* pred   = (const float*)d_in[0];
    const void*  target = d_in[1];
    const float* temp   = (const float*)d_in[2];

    cudaFuncSetAttribute(tile_kernel, cudaFuncAttributeMaxDynamicSharedMemorySize, SMEM_BYTES);

    prep_kernel<<<NROWS / 16, 512>>>(pred, target);
    dim3 grid(NTILE, NTILE);   // 64x64, upper triangle active
    tile_kernel<<<grid, NTHREADS, SMEM_BYTES>>>(temp, (float*)d_out);
}